// round 15
// baseline (speedup 1.0000x reference)
#include <cuda_runtime.h>
#include <cstdint>

// ---------------------------------------------------------------------------
// MyModel_87522843559014: LSTM(B=256,T=512,F=128,H=256) + MLP head
//   reset -> xz -> dummy -> lstm (ncu captures 4th launch) -> head
//   xz: tf32 mma.sync GEMM (R12, 443us).
//   lstm R15 (on R14): warp-local gates via shfl, h exchanged as tf32
//   fragments in global. NEW: no threadfence (release cumulativity over
//   bar.sync), per-thread 4-flag acquire wait (one less bar/step), MMA
//   accumulation split into 4 independent chains (half dep depth).
// ---------------------------------------------------------------------------

typedef unsigned long long ull;

__device__ float g_xz[512u * 256u * 1024u];    // [T][B][4H] fp32
__device__ float g_h[256][256];                // final h (head input)
__device__ uint32_t g_hf[2][16][4096];         // h as tf32 B-fragments, 2 bufs
__device__ unsigned g_flag[16 * 8 * 32];       // per-(group,colblock) flags

__global__ void reset_kernel() {
    if (threadIdx.x < 128) g_flag[threadIdx.x * 32] = 0u;
}
__global__ void dummy_kernel() {}

// ---------------- flag primitives ----------------------------------------------
// post: bar.sync then release-store (cumulative -> covers all threads' stores)
__device__ __forceinline__ void flag_post(int grp, int jt, unsigned id) {
    __syncthreads();
    if (threadIdx.x == 0) {
        asm volatile("st.release.gpu.global.u32 [%0], %1;"
                     :: "l"(&g_flag[(grp * 8 + jt) * 32]), "r"(id) : "memory");
    }
}
// wait: each thread acquire-polls the 4 source blocks its B-fill loads read
__device__ __forceinline__ void flag_wait4(int grp, int s0, unsigned id) {
#pragma unroll
    for (int u = 0; u < 4; u++) {
        const unsigned* f = &g_flag[(grp * 8 + s0 + 2 * u) * 32];
        unsigned v;
        do {
            asm volatile("ld.acquire.gpu.global.u32 %0, [%1];"
                         : "=r"(v) : "l"(f) : "memory");
        } while (v < id);
    }
}

// ---------------- fast activations -------------------------------------------
__device__ __forceinline__ float sigf(float x)     { return 1.f / (1.f + __expf(-x)); }
__device__ __forceinline__ float tanhfast(float x) { return 2.f / (1.f + __expf(-2.f * x)) - 1.f; }

// ---------------- tf32 mma helpers --------------------------------------------
__device__ __forceinline__ uint32_t to_tf32(float f) {
    uint32_t u;
    asm("cvt.rna.tf32.f32 %0, %1;" : "=r"(u) : "f"(f));
    return u;
}
__device__ __forceinline__ void mma_tf32(float* c, const uint32_t* a,
                                         const uint32_t* b) {
    asm volatile(
        "mma.sync.aligned.m16n8k8.row.col.f32.tf32.tf32.f32 "
        "{%0,%1,%2,%3}, {%4,%5,%6,%7}, {%8,%9}, {%0,%1,%2,%3};"
        : "+f"(c[0]), "+f"(c[1]), "+f"(c[2]), "+f"(c[3])
        : "r"(a[0]), "r"(a[1]), "r"(a[2]), "r"(a[3]), "r"(b[0]), "r"(b[1]));
}

// ---------------- input projection GEMM (tf32 mma, R12 unchanged) -------------
#define XZ_SMEM 131072
__global__ void __launch_bounds__(256, 1)
xz_gemm_kernel(const float* __restrict__ x, const float* __restrict__ kern) {
    extern __shared__ char smx[];
    uint4* AF = (uint4*)(smx);
    uint2* BF = (uint2*)(smx + 65536);

    const int tid = threadIdx.x;
    const int wid = tid >> 5, lane = tid & 31;
    const int gid = lane >> 2, tig = lane & 3;
    const int nb = blockIdx.x;
    const int mb = blockIdx.y;
    const int m0 = mb * 128, n0 = nb * 128;

#pragma unroll
    for (int u = 0; u < 16; u++) {
        int idx = tid + u * 256;
        int l = idx & 31, t2 = idx >> 5;
        int i = t2 & 1, km = (t2 >> 1) & 15, mh = t2 >> 5;
        int g2 = l >> 2, t4 = l & 3;
        int mr0 = m0 + mh * 32 + i * 16 + g2;
        int mr1 = mr0 + 8;
        const float* xr0 = x + ((size_t)(mr0 & 255) * 512 + (mr0 >> 8)) * 128;
        const float* xr1 = x + ((size_t)(mr1 & 255) * 512 + (mr1 >> 8)) * 128;
        int k = km * 8 + t4;
        uint4 v;
        v.x = to_tf32(xr0[k]);
        v.y = to_tf32(xr1[k]);
        v.z = to_tf32(xr0[k + 4]);
        v.w = to_tf32(xr1[k + 4]);
        AF[idx] = v;
    }
#pragma unroll
    for (int u = 0; u < 32; u++) {
        int idx = tid + u * 256;
        int l = idx & 31, t2 = idx >> 5;
        int j = t2 & 7, km = (t2 >> 3) & 15, nh = t2 >> 7;
        int n = n0 + nh * 64 + j * 8 + (l >> 2);
        int k = km * 8 + (l & 3);
        uint2 v;
        v.x = to_tf32(kern[(size_t)k * 1024 + n]);
        v.y = to_tf32(kern[(size_t)(k + 4) * 1024 + n]);
        BF[idx] = v;
    }
    __syncthreads();

    const int mh = wid >> 1, nh = wid & 1;
    const uint4* afp = AF + (mh * 16) * 2 * 32 + lane;
    const uint2* bfp = BF + (nh * 16) * 8 * 32 + lane;

    float cacc[2][8][4];
#pragma unroll
    for (int i = 0; i < 2; i++)
#pragma unroll
        for (int j = 0; j < 8; j++)
#pragma unroll
            for (int r = 0; r < 4; r++) cacc[i][j][r] = 0.f;

#pragma unroll
    for (int km = 0; km < 16; km++) {
        uint32_t a[2][4];
#pragma unroll
        for (int i = 0; i < 2; i++) {
            uint4 av = afp[(km * 2 + i) * 32];
            a[i][0] = av.x; a[i][1] = av.y; a[i][2] = av.z; a[i][3] = av.w;
        }
#pragma unroll
        for (int j = 0; j < 8; j++) {
            uint2 bv = bfp[(km * 8 + j) * 32];
            uint32_t b[2] = {bv.x, bv.y};
            mma_tf32(cacc[0][j], a[0], b);
            mma_tf32(cacc[1][j], a[1], b);
        }
    }

#pragma unroll
    for (int i = 0; i < 2; i++) {
        int mr = m0 + mh * 32 + i * 16 + gid;
#pragma unroll
        for (int j = 0; j < 8; j++) {
            int nc = n0 + nh * 64 + j * 8 + tig * 2;
            *(float2*)&g_xz[(size_t)mr * 1024 + nc] =
                make_float2(cacc[i][j][0], cacc[i][j][1]);
            *(float2*)&g_xz[(size_t)(mr + 8) * 1024 + nc] =
                make_float2(cacc[i][j][2], cacc[i][j][3]);
        }
    }
}

// smem: AF staging (131072B) aliases BF (16KB used in loop).
#define SM_TOTAL 131072

// ---------------- persistent LSTM kernel (R15) --------------------------------
// 16 groups x 8 blocks, 256 threads. Warp owns all 4 gates of 4 j's, full
// K=256. Gates via 3-round shfl; cell state in registers; h exchanged as
// tf32 fragments in g_hf.
__global__ void __launch_bounds__(256, 1)
lstm_kernel(const float* __restrict__ rkernel) {
    extern __shared__ char smem[];
    uint4* AF   = (uint4*)(smem);            // staging only (pre-loop)
    uint2* BFu2 = (uint2*)(smem);            // loop: B fragments (16KB)
    uint4* BFu4 = (uint4*)(smem);

    const int tid = threadIdx.x;
    const int wid = tid >> 5, lane = tid & 31;
    const int grp = blockIdx.x >> 3;    // 0..15
    const int jt  = blockIdx.x & 7;     // 0..7
    const int bbase = grp * 16, jbase = jt * 32;
    const int gid = lane >> 2, tig = lane & 3;
    const int g   = gid & 3;            // gate owned by this lane's m-rows
    const int jl  = gid >> 2;           // j-offset low bit
    const int src0 = tid >> 7;          // first of 4 flag sources (0 or 1)

    // ---- stage A fragments (fragment order), copy to registers
    for (int idx = tid; idx < 8192; idx += 256) {
        int l = idx & 31, t2 = idx >> 5;
        int km = t2 & 31, w = t2 >> 5;
        int g2 = l >> 2, t4 = l & 3;
        int col0 = (g2 & 3) * 256 + jbase + w * 4 + (g2 >> 2);
        int col1 = col0 + 2;
        int k = km * 8 + t4;
        uint4 v;
        v.x = to_tf32(rkernel[(size_t)k * 1024 + col0]);
        v.y = to_tf32(rkernel[(size_t)k * 1024 + col1]);
        v.z = to_tf32(rkernel[(size_t)(k + 4) * 1024 + col0]);
        v.w = to_tf32(rkernel[(size_t)(k + 4) * 1024 + col1]);
        AF[idx] = v;
    }
    __syncthreads();

    uint4 areg[32];
    {
        const uint4* afp = AF + wid * 32 * 32 + lane;
#pragma unroll
        for (int km = 0; km < 32; km++) areg[km] = afp[km * 32];
    }
    __syncthreads();   // AF region now reusable as BF

    // zero h0 fragment buffer (par=0) slice, then post id 1
    for (int i = tid; i < 512; i += 256)
        g_hf[0][grp][jt * 512 + i] = 0u;
    flag_post(grp, jt, 1u);

    // per-lane constants
    const int kcol = jbase + wid * 4 + jl + (g & 1) * 2;
    const int n0   = (g >> 1) * 8 + tig * 2;
    const int e0 = ((kcol >> 3) * 2 + (n0 >> 3)) * 64 + (n0 & 7) * 8
                 + (kcol & 3) * 2 + ((kcol >> 2) & 1);
    const int colA = (gid & 3) * 256 + jbase + wid * 4 + (gid >> 2);
    int xoff[2][4];
#pragma unroll
    for (int nt = 0; nt < 2; nt++) {
        int nn = nt * 8 + tig * 2;
        xoff[nt][0] = (bbase + nn) * 1024 + colA;
        xoff[nt][1] = (bbase + nn + 1) * 1024 + colA;
        xoff[nt][2] = (bbase + nn) * 1024 + colA + 2;
        xoff[nt][3] = (bbase + nn + 1) * 1024 + colA + 2;
    }

    float cr0 = 0.f, cr1 = 0.f;
    float xzp[2][4], xzn[2][4];
#pragma unroll
    for (int nt = 0; nt < 2; nt++)
#pragma unroll
        for (int ci = 0; ci < 4; ci++)
            xzp[nt][ci] = __ldcg(&g_xz[xoff[nt][ci]]);

    for (int t = 0; t < 512; t++) {
        const int par = t & 1;

        // wait only on the 4 source blocks whose data this thread will load
        flag_wait4(grp, src0, (unsigned)(t + 1));

        // B-fill: coalesced copy of tf32 fragments (acquire above orders these)
        const uint4* src = (const uint4*)&g_hf[par][grp][0];
#pragma unroll
        for (int u = 0; u < 4; u++) {
            int idx = tid + u * 256;
            uint4 v;
            asm volatile("ld.global.cg.v4.u32 {%0,%1,%2,%3}, [%4];"
                         : "=r"(v.x), "=r"(v.y), "=r"(v.z), "=r"(v.w)
                         : "l"(src + idx));
            BFu4[idx] = v;
        }
        __syncthreads();   // also joins all threads' flag observations

        // 64 MMAs: 4 independent chains (2 n-tiles x 2 km-halves, depth 16)
        float cacc[2][2][4];
#pragma unroll
        for (int nt = 0; nt < 2; nt++)
#pragma unroll
            for (int h = 0; h < 2; h++)
#pragma unroll
                for (int r = 0; r < 4; r++) cacc[nt][h][r] = 0.f;

        const uint2* bfp = BFu2 + lane;
#pragma unroll
        for (int km = 0; km < 16; km++) {
            uint32_t a0[4] = {areg[km].x, areg[km].y, areg[km].z, areg[km].w};
            uint32_t a1[4] = {areg[km + 16].x, areg[km + 16].y,
                              areg[km + 16].z, areg[km + 16].w};
            uint2 bv00 = bfp[(km * 2) * 32];
            uint2 bv01 = bfp[(km * 2 + 1) * 32];
            uint2 bv10 = bfp[((km + 16) * 2) * 32];
            uint2 bv11 = bfp[((km + 16) * 2 + 1) * 32];
            uint32_t b00[2] = {bv00.x, bv00.y};
            uint32_t b01[2] = {bv01.x, bv01.y};
            uint32_t b10[2] = {bv10.x, bv10.y};
            uint32_t b11[2] = {bv11.x, bv11.y};
            mma_tf32(cacc[0][0], a0, b00);
            mma_tf32(cacc[1][0], a0, b01);
            mma_tf32(cacc[0][1], a1, b10);
            mma_tf32(cacc[1][1], a1, b11);
        }
        float cf[2][4];
#pragma unroll
        for (int nt = 0; nt < 2; nt++)
#pragma unroll
            for (int r = 0; r < 4; r++)
                cf[nt][r] = cacc[nt][0][r] + cacc[nt][1][r];

        // add xz, prefetch next xz
#pragma unroll
        for (int nt = 0; nt < 2; nt++)
#pragma unroll
            for (int ci = 0; ci < 4; ci++) cf[nt][ci] += xzp[nt][ci];
        if (t < 511) {
            size_t tb = (size_t)(t + 1) * 256 * 1024;
#pragma unroll
            for (int nt = 0; nt < 2; nt++)
#pragma unroll
                for (int ci = 0; ci < 4; ci++)
                    xzn[nt][ci] = __ldcg(&g_xz[tb + xoff[nt][ci]]);
        }

        // shfl exchange: slot s values = cf[s>>1][(s&1)*2 + v]
        float own0, own1, r10, r11, r20, r21, r30, r31;
        own0 = (g == 0) ? cf[0][0] : (g == 1) ? cf[0][2]
             : (g == 2) ? cf[1][0] : cf[1][2];
        own1 = (g == 0) ? cf[0][1] : (g == 1) ? cf[0][3]
             : (g == 2) ? cf[1][1] : cf[1][3];
#pragma unroll
        for (int k = 1; k <= 3; k++) {
            int s = g ^ k;
            float t0 = (s == 0) ? cf[0][0] : (s == 1) ? cf[0][2]
                     : (s == 2) ? cf[1][0] : cf[1][2];
            float t1 = (s == 0) ? cf[0][1] : (s == 1) ? cf[0][3]
                     : (s == 2) ? cf[1][1] : cf[1][3];
            int srcl = (lane & 0x13) | (s << 2);
            float q0 = __shfl_sync(0xffffffffu, t0, srcl);
            float q1 = __shfl_sync(0xffffffffu, t1, srcl);
            if (k == 1) { r10 = q0; r11 = q1; }
            else if (k == 2) { r20 = q0; r21 = q1; }
            else { r30 = q0; r31 = q1; }
        }
        float zq0[4], zq1[4];
#pragma unroll
        for (int q = 0; q < 4; q++) {
            int kk = g ^ q;
            zq0[q] = (kk == 0) ? own0 : (kk == 1) ? r10 : (kk == 2) ? r20 : r30;
            zq1[q] = (kk == 0) ? own1 : (kk == 1) ? r11 : (kk == 2) ? r21 : r31;
        }

        float cn0 = sigf(zq0[1]) * cr0 + sigf(zq0[0]) * tanhfast(zq0[2]);
        float cn1 = sigf(zq1[1]) * cr1 + sigf(zq1[0]) * tanhfast(zq1[2]);
        cr0 = cn0; cr1 = cn1;
        float h0 = sigf(zq0[3]) * tanhfast(cn0);
        float h1 = sigf(zq1[3]) * tanhfast(cn1);

        if (t < 511) {
            uint32_t* dst = &g_hf[par ^ 1][grp][0];
            dst[e0]     = to_tf32(h0);
            dst[e0 + 8] = to_tf32(h1);
        } else {
            g_h[bbase + n0][kcol]     = h0;
            g_h[bbase + n0 + 1][kcol] = h1;
        }
#pragma unroll
        for (int nt = 0; nt < 2; nt++)
#pragma unroll
            for (int ci = 0; ci < 4; ci++) xzp[nt][ci] = xzn[nt][ci];

        if (t < 511) flag_post(grp, jt, (unsigned)(t + 2));
    }
    // kernel boundary syncs before head
}

// ---------------- MLP head ---------------------------------------------------
__global__ void __launch_bounds__(256)
head_kernel(const float* __restrict__ w1, const float* __restrict__ b1,
            const float* __restrict__ w2, const float* __restrict__ b2,
            float* __restrict__ out) {
    __shared__ float hs[256];
    __shared__ float ys[100];
    const int b = blockIdx.x, tid = threadIdx.x;
    hs[tid] = g_h[b][tid];
    __syncthreads();
    if (tid < 100) {
        float a = b1[tid];
#pragma unroll 4
        for (int k = 0; k < 256; k++) a = fmaf(hs[k], w1[k * 100 + tid], a);
        ys[tid] = fmaxf(a, 0.f);
    }
    __syncthreads();
    if (tid == 0) {
        float s = b2[0];
        for (int j = 0; j < 100; j++) s = fmaf(ys[j], w2[j], s);
        out[b] = s;
    }
}

// ---------------- launch ------------------------------------------------------
extern "C" void kernel_launch(void* const* d_in, const int* in_sizes, int n_in,
                              void* d_out, int out_size) {
    const float* x    = (const float*)d_in[0];
    const float* kern = (const float*)d_in[1];
    const float* rk   = (const float*)d_in[2];
    const float* w1   = (const float*)d_in[3];
    const float* b1   = (const float*)d_in[4];
    const float* w2   = (const float*)d_in[5];
    const float* b2   = (const float*)d_in[6];
    float* out = (float*)d_out;

    cudaFuncSetAttribute(xz_gemm_kernel, cudaFuncAttributeMaxDynamicSharedMemorySize,
                         XZ_SMEM);
    cudaFuncSetAttribute(lstm_kernel, cudaFuncAttributeMaxDynamicSharedMemorySize,
                         SM_TOTAL);

    // order puts ncu's capture (4th launch of cycle) on lstm_kernel
    reset_kernel<<<1, 128>>>();
    dim3 gg(8, 1024);
    xz_gemm_kernel<<<gg, 256, XZ_SMEM>>>(x, kern);
    dummy_kernel<<<1, 1>>>();
    lstm_kernel<<<128, 256, SM_TOTAL>>>(rk);
    head_kernel<<<256, 256>>>(w1, b1, w2, b2, out);
}

// round 16
// speedup vs baseline: 1.1861x; 1.1861x over previous
#include <cuda_runtime.h>
#include <cstdint>

// ---------------------------------------------------------------------------
// MyModel_87522843559014: LSTM(B=256,T=512,F=128,H=256) + MLP head
//   reset -> xz -> dummy -> lstm (ncu captures 4th launch) -> head
//   xz: tf32 mma.sync GEMM (R12, 443us).
//   lstm R16 = R14 skeleton (fused flag barrier, 8 waiter threads) +
//     (a) no threadfence: bar.sync + st.release.gpu cumulativity
//     (b) MMA accumulation split into 4 independent chains (depth 16)
//   (R15's per-thread flag_wait4 identified as the regressor; reverted.)
// ---------------------------------------------------------------------------

typedef unsigned long long ull;

__device__ float g_xz[512u * 256u * 1024u];    // [T][B][4H] fp32
__device__ float g_h[256][256];                // final h (head input)
__device__ uint32_t g_hf[2][16][4096];         // h as tf32 B-fragments, 2 bufs
__device__ unsigned g_flag[16 * 8 * 32];       // per-(group,colblock) flags

__global__ void reset_kernel() {
    if (threadIdx.x < 128) g_flag[threadIdx.x * 32] = 0u;
}
__global__ void dummy_kernel() {}

// ---------------- fused flag barrier (8 blocks/group, 8 waiter threads) -------
// bar.sync before the release-store makes all threads' prior global stores
// cumulative through the release (PTX memory model) — no threadfence needed.
__device__ __forceinline__ void flag_sync(int grp, int jt, unsigned id) {
    __syncthreads();
    if (threadIdx.x == 0) {
        asm volatile("st.release.gpu.global.u32 [%0], %1;"
                     :: "l"(&g_flag[(grp * 8 + jt) * 32]), "r"(id) : "memory");
    }
    if (threadIdx.x < 8) {
        const unsigned* f = &g_flag[(grp * 8 + (int)threadIdx.x) * 32];
        unsigned v;
        do {
            asm volatile("ld.acquire.gpu.global.u32 %0, [%1];"
                         : "=r"(v) : "l"(f) : "memory");
        } while (v < id);
    }
    __syncthreads();
}

// ---------------- fast activations -------------------------------------------
__device__ __forceinline__ float sigf(float x)     { return 1.f / (1.f + __expf(-x)); }
__device__ __forceinline__ float tanhfast(float x) { return 2.f / (1.f + __expf(-2.f * x)) - 1.f; }

// ---------------- tf32 mma helpers --------------------------------------------
__device__ __forceinline__ uint32_t to_tf32(float f) {
    uint32_t u;
    asm("cvt.rna.tf32.f32 %0, %1;" : "=r"(u) : "f"(f));
    return u;
}
__device__ __forceinline__ void mma_tf32(float* c, const uint32_t* a,
                                         const uint32_t* b) {
    asm volatile(
        "mma.sync.aligned.m16n8k8.row.col.f32.tf32.tf32.f32 "
        "{%0,%1,%2,%3}, {%4,%5,%6,%7}, {%8,%9}, {%0,%1,%2,%3};"
        : "+f"(c[0]), "+f"(c[1]), "+f"(c[2]), "+f"(c[3])
        : "r"(a[0]), "r"(a[1]), "r"(a[2]), "r"(a[3]), "r"(b[0]), "r"(b[1]));
}

// ---------------- input projection GEMM (tf32 mma, R12 unchanged) -------------
#define XZ_SMEM 131072
__global__ void __launch_bounds__(256, 1)
xz_gemm_kernel(const float* __restrict__ x, const float* __restrict__ kern) {
    extern __shared__ char smx[];
    uint4* AF = (uint4*)(smx);
    uint2* BF = (uint2*)(smx + 65536);

    const int tid = threadIdx.x;
    const int wid = tid >> 5, lane = tid & 31;
    const int gid = lane >> 2, tig = lane & 3;
    const int nb = blockIdx.x;
    const int mb = blockIdx.y;
    const int m0 = mb * 128, n0 = nb * 128;

#pragma unroll
    for (int u = 0; u < 16; u++) {
        int idx = tid + u * 256;
        int l = idx & 31, t2 = idx >> 5;
        int i = t2 & 1, km = (t2 >> 1) & 15, mh = t2 >> 5;
        int g2 = l >> 2, t4 = l & 3;
        int mr0 = m0 + mh * 32 + i * 16 + g2;
        int mr1 = mr0 + 8;
        const float* xr0 = x + ((size_t)(mr0 & 255) * 512 + (mr0 >> 8)) * 128;
        const float* xr1 = x + ((size_t)(mr1 & 255) * 512 + (mr1 >> 8)) * 128;
        int k = km * 8 + t4;
        uint4 v;
        v.x = to_tf32(xr0[k]);
        v.y = to_tf32(xr1[k]);
        v.z = to_tf32(xr0[k + 4]);
        v.w = to_tf32(xr1[k + 4]);
        AF[idx] = v;
    }
#pragma unroll
    for (int u = 0; u < 32; u++) {
        int idx = tid + u * 256;
        int l = idx & 31, t2 = idx >> 5;
        int j = t2 & 7, km = (t2 >> 3) & 15, nh = t2 >> 7;
        int n = n0 + nh * 64 + j * 8 + (l >> 2);
        int k = km * 8 + (l & 3);
        uint2 v;
        v.x = to_tf32(kern[(size_t)k * 1024 + n]);
        v.y = to_tf32(kern[(size_t)(k + 4) * 1024 + n]);
        BF[idx] = v;
    }
    __syncthreads();

    const int mh = wid >> 1, nh = wid & 1;
    const uint4* afp = AF + (mh * 16) * 2 * 32 + lane;
    const uint2* bfp = BF + (nh * 16) * 8 * 32 + lane;

    float cacc[2][8][4];
#pragma unroll
    for (int i = 0; i < 2; i++)
#pragma unroll
        for (int j = 0; j < 8; j++)
#pragma unroll
            for (int r = 0; r < 4; r++) cacc[i][j][r] = 0.f;

#pragma unroll
    for (int km = 0; km < 16; km++) {
        uint32_t a[2][4];
#pragma unroll
        for (int i = 0; i < 2; i++) {
            uint4 av = afp[(km * 2 + i) * 32];
            a[i][0] = av.x; a[i][1] = av.y; a[i][2] = av.z; a[i][3] = av.w;
        }
#pragma unroll
        for (int j = 0; j < 8; j++) {
            uint2 bv = bfp[(km * 8 + j) * 32];
            uint32_t b[2] = {bv.x, bv.y};
            mma_tf32(cacc[0][j], a[0], b);
            mma_tf32(cacc[1][j], a[1], b);
        }
    }

#pragma unroll
    for (int i = 0; i < 2; i++) {
        int mr = m0 + mh * 32 + i * 16 + gid;
#pragma unroll
        for (int j = 0; j < 8; j++) {
            int nc = n0 + nh * 64 + j * 8 + tig * 2;
            *(float2*)&g_xz[(size_t)mr * 1024 + nc] =
                make_float2(cacc[i][j][0], cacc[i][j][1]);
            *(float2*)&g_xz[(size_t)(mr + 8) * 1024 + nc] =
                make_float2(cacc[i][j][2], cacc[i][j][3]);
        }
    }
}

// smem: AF staging (131072B) aliases BF (16KB used in loop).
#define SM_TOTAL 131072

// ---------------- persistent LSTM kernel (R16) --------------------------------
// 16 groups x 8 blocks, 256 threads. Warp owns all 4 gates of 4 j's, full
// K=256. Gates via 3-round shfl; cell state in registers; h exchanged as
// tf32 fragments in g_hf.
__global__ void __launch_bounds__(256, 1)
lstm_kernel(const float* __restrict__ rkernel) {
    extern __shared__ char smem[];
    uint4* AF   = (uint4*)(smem);            // staging only (pre-loop)
    uint2* BFu2 = (uint2*)(smem);            // loop: B fragments (16KB)
    uint4* BFu4 = (uint4*)(smem);

    const int tid = threadIdx.x;
    const int wid = tid >> 5, lane = tid & 31;
    const int grp = blockIdx.x >> 3;    // 0..15
    const int jt  = blockIdx.x & 7;     // 0..7
    const int bbase = grp * 16, jbase = jt * 32;
    const int gid = lane >> 2, tig = lane & 3;
    const int g   = gid & 3;            // gate owned by this lane's m-rows
    const int jl  = gid >> 2;           // j-offset low bit

    // ---- stage A fragments (fragment order), copy to registers
    for (int idx = tid; idx < 8192; idx += 256) {
        int l = idx & 31, t2 = idx >> 5;
        int km = t2 & 31, w = t2 >> 5;
        int g2 = l >> 2, t4 = l & 3;
        int col0 = (g2 & 3) * 256 + jbase + w * 4 + (g2 >> 2);
        int col1 = col0 + 2;
        int k = km * 8 + t4;
        uint4 v;
        v.x = to_tf32(rkernel[(size_t)k * 1024 + col0]);
        v.y = to_tf32(rkernel[(size_t)k * 1024 + col1]);
        v.z = to_tf32(rkernel[(size_t)(k + 4) * 1024 + col0]);
        v.w = to_tf32(rkernel[(size_t)(k + 4) * 1024 + col1]);
        AF[idx] = v;
    }
    __syncthreads();

    uint4 areg[32];
    {
        const uint4* afp = AF + wid * 32 * 32 + lane;
#pragma unroll
        for (int km = 0; km < 32; km++) areg[km] = afp[km * 32];
    }
    __syncthreads();   // AF region now reusable as BF

    // zero h0 fragment buffer (par=0) slice
    for (int i = tid; i < 512; i += 256)
        g_hf[0][grp][jt * 512 + i] = 0u;
    flag_sync(grp, jt, 1u);

    // per-lane constants
    const int kcol = jbase + wid * 4 + jl + (g & 1) * 2;
    const int n0   = (g >> 1) * 8 + tig * 2;
    const int e0 = ((kcol >> 3) * 2 + (n0 >> 3)) * 64 + (n0 & 7) * 8
                 + (kcol & 3) * 2 + ((kcol >> 2) & 1);
    const int colA = (gid & 3) * 256 + jbase + wid * 4 + (gid >> 2);
    int xoff[2][4];
#pragma unroll
    for (int nt = 0; nt < 2; nt++) {
        int nn = nt * 8 + tig * 2;
        xoff[nt][0] = (bbase + nn) * 1024 + colA;
        xoff[nt][1] = (bbase + nn + 1) * 1024 + colA;
        xoff[nt][2] = (bbase + nn) * 1024 + colA + 2;
        xoff[nt][3] = (bbase + nn + 1) * 1024 + colA + 2;
    }

    float cr0 = 0.f, cr1 = 0.f;
    float xzp[2][4], xzn[2][4];
#pragma unroll
    for (int nt = 0; nt < 2; nt++)
#pragma unroll
        for (int ci = 0; ci < 4; ci++)
            xzp[nt][ci] = __ldcg(&g_xz[xoff[nt][ci]]);

    for (int t = 0; t < 512; t++) {
        const int par = t & 1;

        // B-fill: coalesced copy of tf32 fragments
        const uint4* src = (const uint4*)&g_hf[par][grp][0];
#pragma unroll
        for (int u = 0; u < 4; u++) {
            int idx = tid + u * 256;
            uint4 v;
            asm volatile("ld.global.cg.v4.u32 {%0,%1,%2,%3}, [%4];"
                         : "=r"(v.x), "=r"(v.y), "=r"(v.z), "=r"(v.w)
                         : "l"(src + idx));
            BFu4[idx] = v;
        }
        __syncthreads();

        // 64 MMAs: 4 independent chains (2 n-tiles x 2 km-halves, depth 16)
        float cacc[2][2][4];
#pragma unroll
        for (int nt = 0; nt < 2; nt++)
#pragma unroll
            for (int h = 0; h < 2; h++)
#pragma unroll
                for (int r = 0; r < 4; r++) cacc[nt][h][r] = 0.f;

        const uint2* bfp = BFu2 + lane;
#pragma unroll
        for (int km = 0; km < 16; km++) {
            uint32_t a0[4] = {areg[km].x, areg[km].y, areg[km].z, areg[km].w};
            uint32_t a1[4] = {areg[km + 16].x, areg[km + 16].y,
                              areg[km + 16].z, areg[km + 16].w};
            uint2 bv00 = bfp[(km * 2) * 32];
            uint2 bv01 = bfp[(km * 2 + 1) * 32];
            uint2 bv10 = bfp[((km + 16) * 2) * 32];
            uint2 bv11 = bfp[((km + 16) * 2 + 1) * 32];
            uint32_t b00[2] = {bv00.x, bv00.y};
            uint32_t b01[2] = {bv01.x, bv01.y};
            uint32_t b10[2] = {bv10.x, bv10.y};
            uint32_t b11[2] = {bv11.x, bv11.y};
            mma_tf32(cacc[0][0], a0, b00);
            mma_tf32(cacc[1][0], a0, b01);
            mma_tf32(cacc[0][1], a1, b10);
            mma_tf32(cacc[1][1], a1, b11);
        }
        float cf[2][4];
#pragma unroll
        for (int nt = 0; nt < 2; nt++)
#pragma unroll
            for (int r = 0; r < 4; r++)
                cf[nt][r] = cacc[nt][0][r] + cacc[nt][1][r];

        // add xz, prefetch next xz
#pragma unroll
        for (int nt = 0; nt < 2; nt++)
#pragma unroll
            for (int ci = 0; ci < 4; ci++) cf[nt][ci] += xzp[nt][ci];
        if (t < 511) {
            size_t tb = (size_t)(t + 1) * 256 * 1024;
#pragma unroll
            for (int nt = 0; nt < 2; nt++)
#pragma unroll
                for (int ci = 0; ci < 4; ci++)
                    xzn[nt][ci] = __ldcg(&g_xz[tb + xoff[nt][ci]]);
        }

        // shfl exchange: slot s values = cf[s>>1][(s&1)*2 + v]
        float own0, own1, r10, r11, r20, r21, r30, r31;
        own0 = (g == 0) ? cf[0][0] : (g == 1) ? cf[0][2]
             : (g == 2) ? cf[1][0] : cf[1][2];
        own1 = (g == 0) ? cf[0][1] : (g == 1) ? cf[0][3]
             : (g == 2) ? cf[1][1] : cf[1][3];
#pragma unroll
        for (int k = 1; k <= 3; k++) {
            int s = g ^ k;
            float t0 = (s == 0) ? cf[0][0] : (s == 1) ? cf[0][2]
                     : (s == 2) ? cf[1][0] : cf[1][2];
            float t1 = (s == 0) ? cf[0][1] : (s == 1) ? cf[0][3]
                     : (s == 2) ? cf[1][1] : cf[1][3];
            int srcl = (lane & 0x13) | (s << 2);
            float q0 = __shfl_sync(0xffffffffu, t0, srcl);
            float q1 = __shfl_sync(0xffffffffu, t1, srcl);
            if (k == 1) { r10 = q0; r11 = q1; }
            else if (k == 2) { r20 = q0; r21 = q1; }
            else { r30 = q0; r31 = q1; }
        }
        float zq0[4], zq1[4];
#pragma unroll
        for (int q = 0; q < 4; q++) {
            int kk = g ^ q;
            zq0[q] = (kk == 0) ? own0 : (kk == 1) ? r10 : (kk == 2) ? r20 : r30;
            zq1[q] = (kk == 0) ? own1 : (kk == 1) ? r11 : (kk == 2) ? r21 : r31;
        }

        float cn0 = sigf(zq0[1]) * cr0 + sigf(zq0[0]) * tanhfast(zq0[2]);
        float cn1 = sigf(zq1[1]) * cr1 + sigf(zq1[0]) * tanhfast(zq1[2]);
        cr0 = cn0; cr1 = cn1;
        float h0 = sigf(zq0[3]) * tanhfast(cn0);
        float h1 = sigf(zq1[3]) * tanhfast(cn1);

        if (t < 511) {
            uint32_t* dst = &g_hf[par ^ 1][grp][0];
            dst[e0]     = to_tf32(h0);
            dst[e0 + 8] = to_tf32(h1);
        } else {
            g_h[bbase + n0][kcol]     = h0;
            g_h[bbase + n0 + 1][kcol] = h1;
        }
#pragma unroll
        for (int nt = 0; nt < 2; nt++)
#pragma unroll
            for (int ci = 0; ci < 4; ci++) xzp[nt][ci] = xzn[nt][ci];

        if (t < 511) flag_sync(grp, jt, (unsigned)(t + 2));
    }
    // kernel boundary syncs before head
}

// ---------------- MLP head ---------------------------------------------------
__global__ void __launch_bounds__(256)
head_kernel(const float* __restrict__ w1, const float* __restrict__ b1,
            const float* __restrict__ w2, const float* __restrict__ b2,
            float* __restrict__ out) {
    __shared__ float hs[256];
    __shared__ float ys[100];
    const int b = blockIdx.x, tid = threadIdx.x;
    hs[tid] = g_h[b][tid];
    __syncthreads();
    if (tid < 100) {
        float a = b1[tid];
#pragma unroll 4
        for (int k = 0; k < 256; k++) a = fmaf(hs[k], w1[k * 100 + tid], a);
        ys[tid] = fmaxf(a, 0.f);
    }
    __syncthreads();
    if (tid == 0) {
        float s = b2[0];
        for (int j = 0; j < 100; j++) s = fmaf(ys[j], w2[j], s);
        out[b] = s;
    }
}

// ---------------- launch ------------------------------------------------------
extern "C" void kernel_launch(void* const* d_in, const int* in_sizes, int n_in,
                              void* d_out, int out_size) {
    const float* x    = (const float*)d_in[0];
    const float* kern = (const float*)d_in[1];
    const float* rk   = (const float*)d_in[2];
    const float* w1   = (const float*)d_in[3];
    const float* b1   = (const float*)d_in[4];
    const float* w2   = (const float*)d_in[5];
    const float* b2   = (const float*)d_in[6];
    float* out = (float*)d_out;

    cudaFuncSetAttribute(xz_gemm_kernel, cudaFuncAttributeMaxDynamicSharedMemorySize,
                         XZ_SMEM);
    cudaFuncSetAttribute(lstm_kernel, cudaFuncAttributeMaxDynamicSharedMemorySize,
                         SM_TOTAL);

    // order puts ncu's capture (4th launch of cycle) on lstm_kernel
    reset_kernel<<<1, 128>>>();
    dim3 gg(8, 1024);
    xz_gemm_kernel<<<gg, 256, XZ_SMEM>>>(x, kern);
    dummy_kernel<<<1, 1>>>();
    lstm_kernel<<<128, 256, SM_TOTAL>>>(rk);
    head_kernel<<<256, 256>>>(w1, b1, w2, b2, out);
}